// round 11
// baseline (speedup 1.0000x reference)
#include <cuda_runtime.h>

// LinearViolationAdaption — GB300 sm_103a, round 5
//
// R4 structure (fused single-read-of-A iteration, 96-CTA L2-resident cap,
// atomic work queue, ping-pong depth-2 prefetch, 2 barriers/iter) with the
// dominant FFMA stream converted to packed f32x2 (SASS FFMA2):
//  * A and x loaded as ulonglong2 -> adjacent-column f32 pairs arrive
//    pre-packed in register pairs, no repack instructions
//  * dot products and g += v*A[m,:] both use fma.rn.f32x2
//  * halves the issued-FMA count (1024 -> 512 per lane per iteration)

#define LVA_ALPHA 0.005f
#define LVA_SCALE 0.001f
#define LVA_DELTA 0.1f
#define LVA_ITERS 51   // MAX_ITER + 1

#define LVA_N 512
#define LVA_M 512
#define LVA_NCTA 96
#define LVA_THREADS 512
#define LVA_NWARP (LVA_THREADS / 32)

typedef unsigned long long u64;

__device__ int lva_work_ctr;

__global__ void lva_reset_kernel() { lva_work_ctr = 0; }

// ---- packed f32x2 helpers --------------------------------------------------
__device__ __forceinline__ u64 f2_fma(u64 a, u64 b, u64 c) {
    u64 d;
    asm("fma.rn.f32x2 %0, %1, %2, %3;" : "=l"(d) : "l"(a), "l"(b), "l"(c));
    return d;
}
__device__ __forceinline__ u64 f2_mul(u64 a, u64 b) {
    u64 d;
    asm("mul.rn.f32x2 %0, %1, %2;" : "=l"(d) : "l"(a), "l"(b));
    return d;
}
__device__ __forceinline__ u64 f2_add(u64 a, u64 b) {
    u64 d;
    asm("add.rn.f32x2 %0, %1, %2;" : "=l"(d) : "l"(a), "l"(b));
    return d;
}
__device__ __forceinline__ float f2_hadd(u64 a) {
    float lo, hi;
    asm("mov.b64 {%0, %1}, %2;" : "=f"(lo), "=f"(hi) : "l"(a));
    return lo + hi;
}
__device__ __forceinline__ u64 f2_bcast(float v) {
    u64 d;
    asm("mov.b64 %0, {%1, %1};" : "=l"(d) : "f"(v));
    return d;
}

// two A rows (m, m+16); each row = 4 ulonglong2 = 8 packed column-pairs
struct Buf2 {
    ulonglong2 a0, a1, a2, a3;   // row m
    ulonglong2 b0, b1, b2, b3;   // row m+16

    __device__ __forceinline__ void load(const float* __restrict__ Ap,
                                         int m0, int lane) {
        const ulonglong2* __restrict__ p0 =
            (const ulonglong2*)(Ap + (size_t)m0 * LVA_N);
        const ulonglong2* __restrict__ p1 =
            (const ulonglong2*)(Ap + (size_t)(m0 + 16) * LVA_N);
        a0 = p0[lane]; a1 = p0[lane + 32]; a2 = p0[lane + 64]; a3 = p0[lane + 96];
        b0 = p1[lane]; b1 = p1[lane + 32]; b2 = p1[lane + 64]; b3 = p1[lane + 96];
    }
};

// process 2 rows: viol, vsum, packed g accumulation
__device__ __forceinline__ void body2(const Buf2& B, int m0,
                                      const float* __restrict__ b_sm,
                                      const u64* __restrict__ xp,  // 8 pairs
                                      u64* __restrict__ g,         // 8 pairs
                                      float& vsum)
{
    // dot products: 2 packed chains per row (even/odd pair slots)
    u64 c0 = f2_mul(B.a0.x, xp[0]);
    u64 c1 = f2_mul(B.a0.y, xp[1]);
    u64 c2 = f2_mul(B.b0.x, xp[0]);
    u64 c3 = f2_mul(B.b0.y, xp[1]);
    c0 = f2_fma(B.a1.x, xp[2], c0);  c1 = f2_fma(B.a1.y, xp[3], c1);
    c2 = f2_fma(B.b1.x, xp[2], c2);  c3 = f2_fma(B.b1.y, xp[3], c3);
    c0 = f2_fma(B.a2.x, xp[4], c0);  c1 = f2_fma(B.a2.y, xp[5], c1);
    c2 = f2_fma(B.b2.x, xp[4], c2);  c3 = f2_fma(B.b2.y, xp[5], c3);
    c0 = f2_fma(B.a3.x, xp[6], c0);  c1 = f2_fma(B.a3.y, xp[7], c1);
    c2 = f2_fma(B.b3.x, xp[6], c2);  c3 = f2_fma(B.b3.y, xp[7], c3);
    float d0 = f2_hadd(f2_add(c0, c1));
    float d1 = f2_hadd(f2_add(c2, c3));

    // two interleaved independent butterflies
    #pragma unroll
    for (int off = 16; off; off >>= 1) {
        d0 += __shfl_xor_sync(0xffffffffu, d0, off);
        d1 += __shfl_xor_sync(0xffffffffu, d1, off);
    }

    float v0 = d0 - b_sm[m0];
    float v1 = d1 - b_sm[m0 + 16];
    v0 = v0 > 0.0f ? v0 : 0.0f;
    v1 = v1 > 0.0f ? v1 : 0.0f;
    vsum += v0 + v1;

    u64 vp0 = f2_bcast(v0);
    u64 vp1 = f2_bcast(v1);

    // g += v0*A[m,:] + v1*A[m+16,:]  (packed, 16 FFMA2)
    g[0] = f2_fma(vp0, B.a0.x, g[0]);  g[1] = f2_fma(vp0, B.a0.y, g[1]);
    g[2] = f2_fma(vp0, B.a1.x, g[2]);  g[3] = f2_fma(vp0, B.a1.y, g[3]);
    g[4] = f2_fma(vp0, B.a2.x, g[4]);  g[5] = f2_fma(vp0, B.a2.y, g[5]);
    g[6] = f2_fma(vp0, B.a3.x, g[6]);  g[7] = f2_fma(vp0, B.a3.y, g[7]);
    g[0] = f2_fma(vp1, B.b0.x, g[0]);  g[1] = f2_fma(vp1, B.b0.y, g[1]);
    g[2] = f2_fma(vp1, B.b1.x, g[2]);  g[3] = f2_fma(vp1, B.b1.y, g[3]);
    g[4] = f2_fma(vp1, B.b2.x, g[4]);  g[5] = f2_fma(vp1, B.b2.y, g[5]);
    g[6] = f2_fma(vp1, B.b3.x, g[6]);  g[7] = f2_fma(vp1, B.b3.y, g[7]);
}

__global__ void __launch_bounds__(LVA_THREADS, 1)
lva_fused_kernel(const float* __restrict__ x_in,
                 const float* __restrict__ A,
                 const float* __restrict__ b,
                 float* __restrict__ x_out,
                 int nprob)
{
    __shared__ __align__(16) float x_sm[LVA_N];
    __shared__ float b_sm[LVA_M];
    __shared__ __align__(16) float g_sm[LVA_NWARP * LVA_N];   // 32 KB
    __shared__ float red_sm[LVA_NWARP];
    __shared__ int   prob_sm;

    const int tid  = threadIdx.x;
    const int warp = tid >> 5;
    const int lane = tid & 31;

    for (;;) {
        __syncthreads();   // protect SMEM + prob_sm from previous problem
        if (tid == 0) prob_sm = atomicAdd(&lva_work_ctr, 1);
        __syncthreads();
        const int p = prob_sm;
        if (p >= nprob) return;

        const float* __restrict__ Ap = A + (size_t)p * LVA_M * LVA_N;

        x_sm[tid] = x_in[(size_t)p * LVA_N + tid];
        b_sm[tid] = b[(size_t)p * LVA_M + tid];
        __syncthreads();

        // x pairs for this lane's 16 columns, register-resident
        u64 xp[8];
        {
            const ulonglong2* xq = (const ulonglong2*)x_sm;
            ulonglong2 q0 = xq[lane];
            ulonglong2 q1 = xq[lane + 32];
            ulonglong2 q2 = xq[lane + 64];
            ulonglong2 q3 = xq[lane + 96];
            xp[0] = q0.x; xp[1] = q0.y; xp[2] = q1.x; xp[3] = q1.y;
            xp[4] = q2.x; xp[5] = q2.y; xp[6] = q3.x; xp[7] = q3.y;
        }

        for (int it = 0; it < LVA_ITERS; ++it) {
            u64 g[8] = {0, 0, 0, 0, 0, 0, 0, 0};
            float vsum = 0.0f;

            Buf2 A0, A1;
            A0.load(Ap, warp, lane);

            // ping-pong over 16 bodies (2 rows each)
            #pragma unroll 1
            for (int t = 0; t < 16; t += 2) {
                A1.load(Ap, warp + 32 * ((t + 1) & 15), lane);
                body2(A0, warp + 32 * t, b_sm, xp, g, vsum);
                A0.load(Ap, warp + 32 * ((t + 2) & 15), lane);
                body2(A1, warp + 32 * (t + 1), b_sm, xp, g, vsum);
            }

            // stage per-warp g partials (STS.128, conflict-free; byte layout
            // identical to the float4 staging: pair j covers cols 4*lane..)
            ulonglong2* gp = (ulonglong2*)(g_sm + warp * LVA_N);
            gp[lane]      = make_ulonglong2(g[0], g[1]);
            gp[lane + 32] = make_ulonglong2(g[2], g[3]);
            gp[lane + 64] = make_ulonglong2(g[4], g[5]);
            gp[lane + 96] = make_ulonglong2(g[6], g[7]);
            if (lane == 0) red_sm[warp] = vsum;   // vsum is lane-uniform
            __syncthreads();

            // every thread: total violation (broadcast LDS, uniform branch)
            float vt0 = 0.0f, vt1 = 0.0f;
            #pragma unroll
            for (int w = 0; w < LVA_NWARP; w += 2) {
                vt0 += red_sm[w];
                vt1 += red_sm[w + 1];
            }
            if (vt0 + vt1 < LVA_DELTA) break;   // inactive BEFORE this update

            // column-tid g reduction across warps (two independent chains)
            float gta = 0.0f, gtb = 0.0f;
            #pragma unroll
            for (int w = 0; w < LVA_NWARP; w += 2) {
                gta += g_sm[w * LVA_N + tid];
                gtb += g_sm[(w + 1) * LVA_N + tid];
            }
            float gt = gta + gtb;

            float lr = LVA_ALPHA / (1.0f + LVA_SCALE * gt);
            float xn = x_sm[tid] - lr * gt;
            x_sm[tid] = xn > 0.0f ? xn : 0.0f;
            __syncthreads();

            // reload x pairs
            const ulonglong2* xq = (const ulonglong2*)x_sm;
            ulonglong2 q0 = xq[lane];
            ulonglong2 q1 = xq[lane + 32];
            ulonglong2 q2 = xq[lane + 64];
            ulonglong2 q3 = xq[lane + 96];
            xp[0] = q0.x; xp[1] = q0.y; xp[2] = q1.x; xp[3] = q1.y;
            xp[4] = q2.x; xp[5] = q2.y; xp[6] = q3.x; xp[7] = q3.y;
        }

        x_out[(size_t)p * LVA_N + tid] = x_sm[tid];
    }
}

extern "C" void kernel_launch(void* const* d_in, const int* in_sizes, int n_in,
                              void* d_out, int out_size)
{
    const float* x = (const float*)d_in[0];   // [B,S,N]
    const float* A = (const float*)d_in[1];   // [B,S,M,N]
    const float* b = (const float*)d_in[2];   // [B,S,M]
    float* out = (float*)d_out;               // [B,S,N]

    int nprob = out_size / LVA_N;             // 256
    int ncta  = nprob < LVA_NCTA ? nprob : LVA_NCTA;

    lva_reset_kernel<<<1, 1>>>();
    lva_fused_kernel<<<ncta, LVA_THREADS>>>(x, A, b, out, nprob);
}